// round 17
// baseline (speedup 1.0000x reference)
#include <cuda_runtime.h>
#include <cuda_bf16.h>
#include <cstdint>

#define T_ 512
#define NG 1024            // groups of 32 spans (256 tokens per block-group)

// ---------------- smem layout ----------------
// float indices
#define F_BQKV 0          // 84
#define F_BO   84
#define F_G1   112
#define F_B1L  140
#define F_B1   168        // 256
#define F_B2   424        // 32 (pad zero)
#define F_G2   456
#define F_B2L  488
#define F_PAD  520
#define I_LEN  548        // int[32]
#define I_VAL  580        // int[32]
// byte offsets (16B aligned)
#define XH_B   2560       // X hi [256 tok][36 halves]  (emb-split only)
#define XL_B   20992      // end 39424
#define W1F_B  39424      // W1 frags [16 fc][2 kt][2 nt][32 lane] uint4 = 32768
#define W2F_B  72192      // W2 frags [16 fc][4 nt2][32 lane] uint4 = 32768
#define WQF_B  104960     // Wqkv frags [11 nq][2 kt][32 lane] uint4 = 11264
#define WOF_B  116224     // Wout frags [2 kt][4 nt][32 lane] uint4 = 4096
#define SCR_B  120320     // 16 warps x 1600 floats (QKV scratch [16 tok][100])
#define SCRF   30080
#define SMEM_END_B 222720

__device__ __forceinline__ void mma_bf16(float* d, uint32_t a0, uint32_t a1,
                                         uint32_t a2, uint32_t a3,
                                         uint32_t b0, uint32_t b1) {
    asm volatile(
        "mma.sync.aligned.m16n8k16.row.col.f32.bf16.bf16.f32 "
        "{%0,%1,%2,%3}, {%4,%5,%6,%7}, {%8,%9}, {%0,%1,%2,%3};"
        : "+f"(d[0]), "+f"(d[1]), "+f"(d[2]), "+f"(d[3])
        : "r"(a0), "r"(a1), "r"(a2), "r"(a3), "r"(b0), "r"(b1));
}
__device__ __forceinline__ uint32_t pack_bf2(__nv_bfloat16 lo, __nv_bfloat16 hi) {
    __nv_bfloat162 t(lo, hi);
    return *reinterpret_cast<uint32_t*>(&t);
}
__device__ __forceinline__ void split_bf16(float v, __nv_bfloat16& hi, float& lo) {
    hi = __float2bfloat16(v);
    lo = v - __bfloat162float(hi);
}
// packed split: hi2 = bf16x2(v0 lo-half, v1 hi-half); lo2 = residuals, same layout
__device__ __forceinline__ void split_pack2(float v0, float v1, uint32_t& hi2, uint32_t& lo2) {
    uint32_t hh;
    asm("cvt.rn.bf16x2.f32 %0, %1, %2;" : "=r"(hh) : "f"(v1), "f"(v0));
    const __nv_bfloat162 hb = *reinterpret_cast<const __nv_bfloat162*>(&hh);
    const float l0 = v0 - __bfloat162float(hb.x);
    const float l1 = v1 - __bfloat162float(hb.y);
    uint32_t ll;
    asm("cvt.rn.bf16x2.f32 %0, %1, %2;" : "=r"(ll) : "f"(l1), "f"(l0));
    hi2 = hh;
    lo2 = ll;
}
// pack a (hi,lo) bf16 pair for elements (e0, e0+1) of row `row`
__device__ __forceinline__ uint2 pack_pair(const float* __restrict__ src, int row, int stride,
                                           int e0, int rmax, int emax) {
    float v0 = (row < rmax && e0     < emax) ? src[row * stride + e0]     : 0.0f;
    float v1 = (row < rmax && e0 + 1 < emax) ? src[row * stride + e0 + 1] : 0.0f;
    uint2 r;
    split_pack2(v0, v1, r.x, r.y);
    return r;
}

__global__ __launch_bounds__(512, 1)
void span_mma_kernel(
    const float* __restrict__ emb,
    const int*   __restrict__ span_lengths,
    const int*   __restrict__ num_spans,
    const float* __restrict__ in_proj_w, const float* __restrict__ in_proj_b,
    const float* __restrict__ out_proj_w, const float* __restrict__ out_proj_b,
    const float* __restrict__ ln1_g, const float* __restrict__ ln1_b,
    const float* __restrict__ lin1_w, const float* __restrict__ lin1_b,
    const float* __restrict__ lin2_w, const float* __restrict__ lin2_b,
    const float* __restrict__ ln2_g, const float* __restrict__ ln2_b,
    const float* __restrict__ pad_token,
    float* __restrict__ outp)
{
    extern __shared__ char smc[];
    float* smf = reinterpret_cast<float*>(smc);
    const int tid = threadIdx.x, warp = tid >> 5, lane = tid & 31;

    // zero X tiles (pad cols must be 0)
    {
        int4 z = make_int4(0, 0, 0, 0);
        int4* d = reinterpret_cast<int4*>(smc + XH_B);
        for (int i = tid; i < (W1F_B - XH_B) / 16; i += 512) d[i] = z;
    }
    for (int i = tid; i < 84; i += 512) smf[F_BQKV + i] = in_proj_b[i];
    if (tid < 256) smf[F_B1 + tid] = lin1_b[tid];
    if (tid < 32) {
        smf[F_B2 + tid]  = (tid < 28) ? lin2_b[tid] : 0.0f;
        smf[F_G2 + tid]  = (tid < 28) ? ln2_g[tid]  : 0.0f;
        smf[F_B2L + tid] = (tid < 28) ? ln2_b[tid]  : 0.0f;
    }
    if (tid < 28) {
        smf[F_BO + tid]  = out_proj_b[tid];
        smf[F_G1 + tid]  = ln1_g[tid];
        smf[F_B1L + tid] = ln1_b[tid];
        smf[F_PAD + tid] = pad_token[tid];
    }
    // ---- stage weights in FRAGMENT order (uint4 = b0h,b1h,b0l,b1l) ----
    for (int idx = tid; idx < 2048; idx += 512) {        // W1 [256 f][28 e]
        const int ln = idx & 31, nt = (idx >> 5) & 1, kt = (idx >> 6) & 1, fc = idx >> 7;
        const int row = fc * 16 + nt * 8 + (ln >> 2);
        const int e0 = kt * 16 + 2 * (ln & 3);
        uint2 p0 = pack_pair(lin1_w, row, 28, e0, 256, 28);
        uint2 p1 = pack_pair(lin1_w, row, 28, e0 + 8, 256, 28);
        reinterpret_cast<uint4*>(smc + W1F_B)[idx] = make_uint4(p0.x, p1.x, p0.y, p1.y);
    }
    for (int idx = tid; idx < 2048; idx += 512) {        // W2 [28 e][256 f] (B rows = e)
        const int ln = idx & 31, nt2 = (idx >> 5) & 3, fc = idx >> 7;
        const int row = nt2 * 8 + (ln >> 2);
        const int f0 = fc * 16 + 2 * (ln & 3);
        uint2 p0 = pack_pair(lin2_w, row, 256, f0, 28, 256);
        uint2 p1 = pack_pair(lin2_w, row, 256, f0 + 8, 28, 256);
        reinterpret_cast<uint4*>(smc + W2F_B)[idx] = make_uint4(p0.x, p1.x, p0.y, p1.y);
    }
    for (int idx = tid; idx < 704; idx += 512) {         // Wqkv [84 r][28 e]
        const int ln = idx & 31, kt = (idx >> 5) & 1, nq = idx >> 6;
        const int row = nq * 8 + (ln >> 2);
        const int e0 = kt * 16 + 2 * (ln & 3);
        uint2 p0 = pack_pair(in_proj_w, row, 28, e0, 84, 28);
        uint2 p1 = pack_pair(in_proj_w, row, 28, e0 + 8, 84, 28);
        reinterpret_cast<uint4*>(smc + WQF_B)[idx] = make_uint4(p0.x, p1.x, p0.y, p1.y);
    }
    for (int idx = tid; idx < 256; idx += 512) {         // Wout [28 r][28 e]
        const int ln = idx & 31, nt = (idx >> 5) & 3, kt = idx >> 7;
        const int row = nt * 8 + (ln >> 2);
        const int e0 = kt * 16 + 2 * (ln & 3);
        uint2 p0 = pack_pair(out_proj_w, row, 28, e0, 28, 28);
        uint2 p1 = pack_pair(out_proj_w, row, 28, e0 + 8, 28, 28);
        reinterpret_cast<uint4*>(smc + WOF_B)[idx] = make_uint4(p0.x, p1.x, p0.y, p1.y);
    }
    __syncthreads();

    uint32_t* XHw = reinterpret_cast<uint32_t*>(smc + XH_B);
    uint32_t* XLw = reinterpret_cast<uint32_t*>(smc + XL_B);
    const uint4* W1F = reinterpret_cast<const uint4*>(smc + W1F_B);
    const uint4* W2F = reinterpret_cast<const uint4*>(smc + W2F_B);
    const uint4* WQF = reinterpret_cast<const uint4*>(smc + WQF_B);
    const uint4* WOF = reinterpret_cast<const uint4*>(smc + WOF_B);
    int* lens = reinterpret_cast<int*>(smf + I_LEN);
    int* vld  = reinterpret_cast<int*>(smf + I_VAL);

    const int l = lane & 7, h = lane >> 3, e0h = h * 7;
    const int gq = lane >> 2, tq = lane & 3;
    const int m0 = warp * 16;
    float* QW = smf + SCRF + warp * 1600;                 // [16 tok][100]: Q@0 K@32 V@64
    uint32_t* QWu = reinterpret_cast<uint32_t*>(QW);
    char* aobase = smc + SCR_B + warp * 6400;             // AO split lives in K slot

    for (int g = blockIdx.x; g < NG; g += gridDim.x) {
        // ---- (a) emb -> X bf16 hi/lo tiles (warp-private 16 tokens) ----
        {
            const float2* esrc = reinterpret_cast<const float2*>(emb + (g * 32 + warp * 2) * 224);
#pragma unroll
            for (int k2 = 0; k2 < 7; k2++) {
                const int idx2 = lane + k2 * 32;
                float2 v = esrc[idx2];
                const int fi = idx2 * 2;
                const int tok = fi / 28, e = fi % 28;
                const int word = (m0 + tok) * 18 + e / 2;
                split_pack2(v.x, v.y, XHw[word], XLw[word]);
            }
        }
        __syncwarp();

        // ---- (b) GEMM_QKV: [16 x 32] x Wqkv^T[88 x 32] ----
        {
            uint32_t ah[2][4], al[2][4];
#pragma unroll
            for (int kt = 0; kt < 2; kt++) {
                const int w0 = (m0 + gq) * 18 + kt * 8 + tq;
                ah[kt][0] = XHw[w0];       ah[kt][1] = XHw[w0 + 144];
                ah[kt][2] = XHw[w0 + 4];   ah[kt][3] = XHw[w0 + 148];
                al[kt][0] = XLw[w0];       al[kt][1] = XLw[w0 + 144];
                al[kt][2] = XLw[w0 + 4];   al[kt][3] = XLw[w0 + 148];
            }
#pragma unroll
            for (int nq = 0; nq < 11; nq++) {
                float d[4] = {0.0f, 0.0f, 0.0f, 0.0f};
#pragma unroll
                for (int kt = 0; kt < 2; kt++) {
                    const uint4 wf = WQF[(nq * 2 + kt) * 32 + lane];
                    mma_bf16(d, ah[kt][0], ah[kt][1], ah[kt][2], ah[kt][3], wf.x, wf.y);
                    mma_bf16(d, al[kt][0], al[kt][1], al[kt][2], al[kt][3], wf.x, wf.y);
                    mma_bf16(d, ah[kt][0], ah[kt][1], ah[kt][2], ah[kt][3], wf.z, wf.w);
                }
                const int c0 = nq * 8 + 2 * tq;
                if (c0 < 84) {
                    const int qk = c0 / 28, r = c0 % 28;
                    const int off = qk * 32 + (r / 7) * 8 + (r % 7);
                    const float bz = smf[F_BQKV + c0];
                    QW[gq * 100 + off]       = d[0] + bz;
                    QW[(gq + 8) * 100 + off] = d[2] + bz;
                }
                const int c1 = c0 + 1;
                if (c1 < 84) {
                    const int qk = c1 / 28, r = c1 % 28;
                    const int off = qk * 32 + (r / 7) * 8 + (r % 7);
                    const float bz = smf[F_BQKV + c1];
                    QW[gq * 100 + off]       = d[1] + bz;
                    QW[(gq + 8) * 100 + off] = d[3] + bz;
                }
            }
        }
        __syncwarp();

        // ---- (c) attention, BOTH spans interleaved (2x ILP on softmax chains) ----
        {
            const int span0 = g * 32 + warp * 2;
            const int len0 = span_lengths[span0];
            const int len1 = span_lengths[span0 + 1];
            const int tok0 = l, tok1 = 8 + l;

            float q0[7], q1[7];
            {
                const float4 a0 = *reinterpret_cast<const float4*>(QW + tok0 * 100 + h * 8);
                const float4 b0 = *reinterpret_cast<const float4*>(QW + tok0 * 100 + h * 8 + 4);
                const float4 a1 = *reinterpret_cast<const float4*>(QW + tok1 * 100 + h * 8);
                const float4 b1 = *reinterpret_cast<const float4*>(QW + tok1 * 100 + h * 8 + 4);
                q0[0] = a0.x; q0[1] = a0.y; q0[2] = a0.z; q0[3] = a0.w;
                q0[4] = b0.x; q0[5] = b0.y; q0[6] = b0.z;
                q1[0] = a1.x; q1[1] = a1.y; q1[2] = a1.z; q1[3] = a1.w;
                q1[4] = b1.x; q1[5] = b1.y; q1[6] = b1.z;
            }
            float s0[8], s1[8];
#pragma unroll
            for (int kk = 0; kk < 8; kk++) {
                const float4 k0a = *reinterpret_cast<const float4*>(QW + kk * 100 + 32 + h * 8);
                const float4 k0b = *reinterpret_cast<const float4*>(QW + kk * 100 + 32 + h * 8 + 4);
                const float4 k1a = *reinterpret_cast<const float4*>(QW + (8 + kk) * 100 + 32 + h * 8);
                const float4 k1b = *reinterpret_cast<const float4*>(QW + (8 + kk) * 100 + 32 + h * 8 + 4);
                float acc0 = q0[0] * k0a.x + q0[1] * k0a.y + q0[2] * k0a.z + q0[3] * k0a.w
                           + q0[4] * k0b.x + q0[5] * k0b.y + q0[6] * k0b.z;
                float acc1 = q1[0] * k1a.x + q1[1] * k1a.y + q1[2] * k1a.z + q1[3] * k1a.w
                           + q1[4] * k1b.x + q1[5] * k1b.y + q1[6] * k1b.z;
                s0[kk] = (kk < len0) ? acc0 * 0.3779644730092272f : -1e9f;
                s1[kk] = (kk < len1) ? acc1 * 0.3779644730092272f : -1e9f;
            }
            __syncwarp();   // ALL K reads (both spans) done before K slot reused for AO
            float mx0 = s0[0], mx1 = s1[0];
#pragma unroll
            for (int kk = 1; kk < 8; kk++) { mx0 = fmaxf(mx0, s0[kk]); mx1 = fmaxf(mx1, s1[kk]); }
            float ps0 = 0.0f, ps1 = 0.0f;
#pragma unroll
            for (int kk = 0; kk < 8; kk++) {
                s0[kk] = __expf(s0[kk] - mx0); ps0 += s0[kk];
                s1[kk] = __expf(s1[kk] - mx1); ps1 += s1[kk];
            }
            const float pi0 = 1.0f / ps0, pi1 = 1.0f / ps1;
            float ao0[7], ao1[7];
#pragma unroll
            for (int d = 0; d < 7; d++) { ao0[d] = 0.0f; ao1[d] = 0.0f; }
#pragma unroll
            for (int kk = 0; kk < 8; kk++) {
                const float4 v0a = *reinterpret_cast<const float4*>(QW + kk * 100 + 64 + h * 8);
                const float4 v0b = *reinterpret_cast<const float4*>(QW + kk * 100 + 64 + h * 8 + 4);
                const float4 v1a = *reinterpret_cast<const float4*>(QW + (8 + kk) * 100 + 64 + h * 8);
                const float4 v1b = *reinterpret_cast<const float4*>(QW + (8 + kk) * 100 + 64 + h * 8 + 4);
                ao0[0] = fmaf(s0[kk], v0a.x, ao0[0]); ao1[0] = fmaf(s1[kk], v1a.x, ao1[0]);
                ao0[1] = fmaf(s0[kk], v0a.y, ao0[1]); ao1[1] = fmaf(s1[kk], v1a.y, ao1[1]);
                ao0[2] = fmaf(s0[kk], v0a.z, ao0[2]); ao1[2] = fmaf(s1[kk], v1a.z, ao1[2]);
                ao0[3] = fmaf(s0[kk], v0a.w, ao0[3]); ao1[3] = fmaf(s1[kk], v1a.w, ao1[3]);
                ao0[4] = fmaf(s0[kk], v0b.x, ao0[4]); ao1[4] = fmaf(s1[kk], v1b.x, ao1[4]);
                ao0[5] = fmaf(s0[kk], v0b.y, ao0[5]); ao1[5] = fmaf(s1[kk], v1b.y, ao1[5]);
                ao0[6] = fmaf(s0[kk], v0b.z, ao0[6]); ao1[6] = fmaf(s1[kk], v1b.z, ao1[6]);
            }
#pragma unroll
            for (int d = 0; d < 7; d++) {
                const int e = e0h + d;
                __nv_bfloat16 h0; float l0f; split_bf16(ao0[d] * pi0, h0, l0f);
                __nv_bfloat16 h1; float l1f; split_bf16(ao1[d] * pi1, h1, l1f);
                *reinterpret_cast<__nv_bfloat16*>(aobase + tok0 * 400 + 128 + e * 2) = h0;
                *reinterpret_cast<__nv_bfloat16*>(aobase + tok0 * 400 + 192 + e * 2) = __float2bfloat16(l0f);
                *reinterpret_cast<__nv_bfloat16*>(aobase + tok1 * 400 + 128 + e * 2) = h1;
                *reinterpret_cast<__nv_bfloat16*>(aobase + tok1 * 400 + 192 + e * 2) = __float2bfloat16(l1f);
            }
            if (lane == 0) {
                lens[warp * 2]     = len0;
                lens[warp * 2 + 1] = len1;
                const int t0 = span0 & (T_ - 1);
                vld[warp * 2]     = (t0     < num_spans[span0 >> 9])       ? 1 : 0;
                vld[warp * 2 + 1] = (t0 + 1 < num_spans[(span0 + 1) >> 9]) ? 1 : 0;
            }
        }
        // zero AO pad cols 28-31 (stale K data): floats 46,47 (AOH) / 62,63 (AOL)
        QW[(lane >> 1) * 100 + 46 + (lane & 1)] = 0.0f;
        QW[(lane >> 1) * 100 + 62 + (lane & 1)] = 0.0f;
        __syncwarp();

        // xn fragment registers (filled by GEMM_O, consumed by FFN + epilogue)
        uint32_t ah[2][4], al[2][4];

        // ---- (d) GEMM_O: [16 x 32] x Wout^T[32 x 32]; +bias +residual +LN1 -> ah/al regs ----
        {
            uint32_t aoh[2][4], aol[2][4];
#pragma unroll
            for (int kt = 0; kt < 2; kt++) {
                const int w0 = gq * 100 + 32 + kt * 8 + tq;
                aoh[kt][0] = QWu[w0];        aoh[kt][1] = QWu[w0 + 800];
                aoh[kt][2] = QWu[w0 + 4];    aoh[kt][3] = QWu[w0 + 804];
                aol[kt][0] = QWu[w0 + 16];   aol[kt][1] = QWu[w0 + 816];
                aol[kt][2] = QWu[w0 + 20];   aol[kt][3] = QWu[w0 + 820];
            }
            float dy[4][4];
#pragma unroll
            for (int nt = 0; nt < 4; nt++)
#pragma unroll
                for (int r = 0; r < 4; r++) dy[nt][r] = 0.0f;
#pragma unroll
            for (int kt = 0; kt < 2; kt++)
#pragma unroll
                for (int nt = 0; nt < 4; nt++) {
                    const uint4 wf = WOF[(kt * 4 + nt) * 32 + lane];
                    mma_bf16(dy[nt], aoh[kt][0], aoh[kt][1], aoh[kt][2], aoh[kt][3], wf.x, wf.y);
                    mma_bf16(dy[nt], aol[kt][0], aol[kt][1], aol[kt][2], aol[kt][3], wf.x, wf.y);
                    mma_bf16(dy[nt], aoh[kt][0], aoh[kt][1], aoh[kt][2], aoh[kt][3], wf.z, wf.w);
                }
            // bias + residual; LN1 stats for tokens gq (A) and gq+8 (B)
            const float* ebase = emb + (g * 32 + warp * 2) * 224;
            float yA[8], yB[8];
            float sA = 0.0f, qA2 = 0.0f, sB = 0.0f, qB2 = 0.0f;
#pragma unroll
            for (int nt = 0; nt < 4; nt++) {
                const int e0 = nt * 8 + 2 * tq;
                const bool ok = (nt < 3) || (tq < 2);
                float2 rA = make_float2(0.0f, 0.0f), rB = make_float2(0.0f, 0.0f);
                float bo0 = 0.0f, bo1 = 0.0f;
                if (ok) {
                    rA = *reinterpret_cast<const float2*>(ebase + gq * 28 + e0);
                    rB = *reinterpret_cast<const float2*>(ebase + (gq + 8) * 28 + e0);
                    bo0 = smf[F_BO + e0];
                    bo1 = smf[F_BO + e0 + 1];
                }
                float a0 = ok ? (dy[nt][0] + bo0 + rA.x) : 0.0f;
                float a1 = ok ? (dy[nt][1] + bo1 + rA.y) : 0.0f;
                float b0 = ok ? (dy[nt][2] + bo0 + rB.x) : 0.0f;
                float b1 = ok ? (dy[nt][3] + bo1 + rB.y) : 0.0f;
                yA[nt * 2] = a0; yA[nt * 2 + 1] = a1;
                yB[nt * 2] = b0; yB[nt * 2 + 1] = b1;
                sA += a0 + a1; qA2 += a0 * a0 + a1 * a1;
                sB += b0 + b1; qB2 += b0 * b0 + b1 * b1;
            }
            sA += __shfl_xor_sync(0xffffffffu, sA, 1); qA2 += __shfl_xor_sync(0xffffffffu, qA2, 1);
            sA += __shfl_xor_sync(0xffffffffu, sA, 2); qA2 += __shfl_xor_sync(0xffffffffu, qA2, 2);
            sB += __shfl_xor_sync(0xffffffffu, sB, 1); qB2 += __shfl_xor_sync(0xffffffffu, qB2, 1);
            sB += __shfl_xor_sync(0xffffffffu, sB, 2); qB2 += __shfl_xor_sync(0xffffffffu, qB2, 2);
            const float muA = sA * (1.0f / 28.0f), muB = sB * (1.0f / 28.0f);
            const float rsA = rsqrtf(fmaxf(qA2 * (1.0f / 28.0f) - muA * muA, 0.0f) + 1e-5f);
            const float rsB = rsqrtf(fmaxf(qB2 * (1.0f / 28.0f) - muB * muB, 0.0f) + 1e-5f);
#pragma unroll
            for (int nt = 0; nt < 4; nt++) {
                const int e0 = nt * 8 + 2 * tq;
                const bool ok = (nt < 3) || (tq < 2);
                const int ktX = nt >> 1, sl0 = (nt & 1) << 1;
                if (ok) {
                    const float g10 = smf[F_G1 + e0], g11 = smf[F_G1 + e0 + 1];
                    const float bl0 = smf[F_B1L + e0], bl1 = smf[F_B1L + e0 + 1];
                    float xA0 = (yA[nt * 2]     - muA) * rsA * g10 + bl0;
                    float xA1 = (yA[nt * 2 + 1] - muA) * rsA * g11 + bl1;
                    float xB0 = (yB[nt * 2]     - muB) * rsB * g10 + bl0;
                    float xB1 = (yB[nt * 2 + 1] - muB) * rsB * g11 + bl1;
                    split_pack2(xA0, xA1, ah[ktX][sl0],     al[ktX][sl0]);
                    split_pack2(xB0, xB1, ah[ktX][sl0 + 1], al[ktX][sl0 + 1]);
                } else {
                    ah[ktX][sl0] = 0u; ah[ktX][sl0 + 1] = 0u;
                    al[ktX][sl0] = 0u; al[ktX][sl0 + 1] = 0u;
                }
            }
        }
        __syncwarp();   // QW reads complete before next group's scatter

        // ---------------- PHASE 2: FFN via mma.sync (A-frags already in ah/al) ----------------
        float d2[4][4];
#pragma unroll
        for (int nt = 0; nt < 4; nt++)
#pragma unroll
            for (int r = 0; r < 4; r++) d2[nt][r] = 0.0f;

#pragma unroll 4
        for (int fc = 0; fc < 16; fc++) {
            float d1[2][4];
#pragma unroll
            for (int nt = 0; nt < 2; nt++)
#pragma unroll
                for (int r = 0; r < 4; r++) d1[nt][r] = 0.0f;
#pragma unroll
            for (int kt = 0; kt < 2; kt++)
#pragma unroll
                for (int nt = 0; nt < 2; nt++) {
                    const uint4 wf = W1F[((fc * 2 + kt) * 2 + nt) * 32 + lane];
                    mma_bf16(d1[nt], ah[kt][0], ah[kt][1], ah[kt][2], ah[kt][3], wf.x, wf.y);
                    mma_bf16(d1[nt], al[kt][0], al[kt][1], al[kt][2], al[kt][3], wf.x, wf.y);
                    mma_bf16(d1[nt], ah[kt][0], ah[kt][1], ah[kt][2], ah[kt][3], wf.z, wf.w);
                }
            uint32_t a2h[4], a2l[4];
#pragma unroll
            for (int nt = 0; nt < 2; nt++) {
                const int fe = fc * 16 + nt * 8 + 2 * tq;
                const float bz0 = smf[F_B1 + fe], bz1 = smf[F_B1 + fe + 1];
                float h0 = fmaxf(d1[nt][0] + bz0, 0.0f);
                float h1 = fmaxf(d1[nt][1] + bz1, 0.0f);
                float h2 = fmaxf(d1[nt][2] + bz0, 0.0f);
                float h3 = fmaxf(d1[nt][3] + bz1, 0.0f);
                split_pack2(h0, h1, a2h[nt * 2 + 0], a2l[nt * 2 + 0]);
                split_pack2(h2, h3, a2h[nt * 2 + 1], a2l[nt * 2 + 1]);
            }
#pragma unroll
            for (int nt2 = 0; nt2 < 4; nt2++) {
                const uint4 wf = W2F[(fc * 4 + nt2) * 32 + lane];
                mma_bf16(d2[nt2], a2h[0], a2h[1], a2h[2], a2h[3], wf.x, wf.y);
                mma_bf16(d2[nt2], a2l[0], a2l[1], a2l[2], a2l[3], wf.x, wf.y);
                mma_bf16(d2[nt2], a2h[0], a2h[1], a2h[2], a2h[3], wf.z, wf.w);
            }
        }

        // ---------------- EPILOGUE: one span at a time (xn from ah/al regs) -------------
#pragma unroll
        for (int sp2 = 0; sp2 < 2; sp2++) {
            const int sl = warp * 2 + sp2;
            const int c0 = sp2 * 2;
            float v[8];
            float ssum = 0.0f, sq = 0.0f;
#pragma unroll
            for (int nt = 0; nt < 4; nt++) {
                const int e0 = nt * 8 + 2 * tq;
                const bool ok = (nt < 3) || (tq < 2);
                const int ktE = nt >> 1, slot = ((nt & 1) << 1) + sp2;
                const uint32_t uh = ah[ktE][slot];
                const uint32_t ul = al[ktE][slot];
                const __nv_bfloat162 bh = *reinterpret_cast<const __nv_bfloat162*>(&uh);
                const __nv_bfloat162 bl = *reinterpret_cast<const __nv_bfloat162*>(&ul);
                const float xn0 = __bfloat162float(bh.x) + __bfloat162float(bl.x);
                const float xn1 = __bfloat162float(bh.y) + __bfloat162float(bl.y);
                float a0 = ok ? (d2[nt][c0]     + smf[F_B2 + e0]     + xn0) : 0.0f;
                float a1 = ok ? (d2[nt][c0 + 1] + smf[F_B2 + e0 + 1] + xn1) : 0.0f;
                v[nt * 2] = a0; v[nt * 2 + 1] = a1;
                ssum += a0 + a1; sq += a0 * a0 + a1 * a1;
            }
            ssum += __shfl_xor_sync(0xffffffffu, ssum, 1); sq += __shfl_xor_sync(0xffffffffu, sq, 1);
            ssum += __shfl_xor_sync(0xffffffffu, ssum, 2); sq += __shfl_xor_sync(0xffffffffu, sq, 2);
            const float mu = ssum * (1.0f / 28.0f);
            const float rs = rsqrtf(fmaxf(sq * (1.0f / 28.0f) - mu * mu, 0.0f) + 1e-5f);
            const int len = lens[sl];
            const float m = (gq < len) ? 1.0f : 0.0f;
            float pz[8];
#pragma unroll
            for (int nt = 0; nt < 4; nt++) {
                const int e0 = nt * 8 + 2 * tq;
                const bool ok = (nt < 3) || (tq < 2);
                pz[nt * 2]     = ok ? ((v[nt * 2]     - mu) * rs * smf[F_G2 + e0]     + smf[F_B2L + e0])     * m : 0.0f;
                pz[nt * 2 + 1] = ok ? ((v[nt * 2 + 1] - mu) * rs * smf[F_G2 + e0 + 1] + smf[F_B2L + e0 + 1]) * m : 0.0f;
            }
#pragma unroll
            for (int i = 0; i < 8; i++) {
                float a = pz[i];
                a += __shfl_xor_sync(0xffffffffu, a, 4);
                a += __shfl_xor_sync(0xffffffffu, a, 8);
                a += __shfl_xor_sync(0xffffffffu, a, 16);
                pz[i] = a;
            }
            if (lane < 4) {
                const float il = 1.0f / (float)len;
                const int sp = g * 32 + sl;
                const int okv = vld[sl];
#pragma unroll
                for (int nt = 0; nt < 4; nt++) {
                    const int e0 = nt * 8 + 2 * tq;
                    if ((nt < 3) || (tq < 2)) {
                        outp[sp * 28 + e0]     = okv ? pz[nt * 2] * il     : smf[F_PAD + e0];
                        outp[sp * 28 + e0 + 1] = okv ? pz[nt * 2 + 1] * il : smf[F_PAD + e0 + 1];
                    }
                }
            }
        }
        __syncwarp();
    }
}

extern "C" void kernel_launch(void* const* d_in, const int* in_sizes, int n_in,
                              void* d_out, int out_size) {
    const float* emb          = (const float*)d_in[0];
    const int*   span_lengths = (const int*)  d_in[1];
    const int*   num_spans    = (const int*)  d_in[2];
    const float* in_proj_w    = (const float*)d_in[3];
    const float* in_proj_b    = (const float*)d_in[4];
    const float* out_proj_w   = (const float*)d_in[5];
    const float* out_proj_b   = (const float*)d_in[6];
    const float* ln1_g        = (const float*)d_in[7];
    const float* ln1_b        = (const float*)d_in[8];
    const float* lin1_w       = (const float*)d_in[9];
    const float* lin1_b       = (const float*)d_in[10];
    const float* lin2_w       = (const float*)d_in[11];
    const float* lin2_b       = (const float*)d_in[12];
    const float* ln2_g        = (const float*)d_in[13];
    const float* ln2_b        = (const float*)d_in[14];
    const float* pad_token    = (const float*)d_in[15];
    float* outp = (float*)d_out;

    cudaFuncSetAttribute(span_mma_kernel,
                         cudaFuncAttributeMaxDynamicSharedMemorySize, SMEM_END_B);

    span_mma_kernel<<<148, 512, SMEM_END_B>>>(
        emb, span_lengths, num_spans,
        in_proj_w, in_proj_b, out_proj_w, out_proj_b,
        ln1_g, ln1_b, lin1_w, lin1_b, lin2_w, lin2_b,
        ln2_g, ln2_b, pad_token, outp);
}